// round 2
// baseline (speedup 1.0000x reference)
#include <cuda_runtime.h>
#include <cstdint>

#define SEQ 4096
#define HD 32
#define NH 8
#define BATCH 2

// Scratch (static device globals: allowed; no runtime allocation)
__device__ float g_q[BATCH*NH*SEQ*HD];
__device__ float g_k[BATCH*NH*SEQ*HD];
__device__ float g_v[BATCH*NH*SEQ*HD];
__device__ float g_o[BATCH*SEQ*NH*HD];   // [b][n][h*32+d]  (heads concatenated)

// tf32 round (cvt.rna.tf32.f32 requires .b32 destination), returned as float bits
__device__ __forceinline__ float to_tf32(float x){
    uint32_t r; asm("cvt.rna.tf32.f32 %0, %1;" : "=r"(r) : "f"(x));
    return __uint_as_float(r);
}
__device__ __forceinline__ float ex2(float x){
    float y; asm("ex2.approx.f32 %0, %1;" : "=f"(y) : "f"(x)); return y;
}
__device__ __forceinline__ uint32_t fu(float x){ return __float_as_uint(x); }

// D = A(16x8,row) * B(8x8,col) + D, tf32 inputs, f32 accum
__device__ __forceinline__ void mma8(float* c, const uint32_t* a, const uint32_t* b){
    asm volatile("mma.sync.aligned.m16n8k8.row.col.f32.tf32.tf32.f32 "
        "{%0,%1,%2,%3}, {%4,%5,%6,%7}, {%8,%9}, {%0,%1,%2,%3};\n"
        : "+f"(c[0]), "+f"(c[1]), "+f"(c[2]), "+f"(c[3])
        : "r"(a[0]), "r"(a[1]), "r"(a[2]), "r"(a[3]), "r"(b[0]), "r"(b[1]));
}

// ---------------------------------------------------------------------------
// Generic tf32 GEMM:  C[M,Nout] = A[M,K] * W[K,Nout] + bias
// MODE 0: A = x, scatter output into g_q/g_k/g_v ([bh][n][d] layout)
// MODE 1: A = g_o, write Out[r*256 + c]
// BM=BN=64, BK=32, 128 threads (2x2 warps, each warp 32x32)
// ---------------------------------------------------------------------------
template<int MODE>
__global__ __launch_bounds__(128) void gemm_kernel(
    const float* __restrict__ Ain, const float* __restrict__ W,
    const float* __restrict__ bias, float* __restrict__ Out,
    int M, int Nout, int K)
{
    __shared__ float As[64][36];   // pad 36: A-frag LDS conflict-free (bank=4r+c)
    __shared__ float Bs[32][72];   // pad 72: B-frag LDS conflict-free (bank=8r+c)

    const float* A = (MODE == 1) ? (const float*)g_o : Ain;

    int tid = threadIdx.x;
    int warp = tid >> 5, lane = tid & 31;
    int wm = warp >> 1, wn = warp & 1;
    int g = lane >> 2, tg = lane & 3;
    int row0 = blockIdx.y * 64, col0 = blockIdx.x * 64;

    float acc[2][4][4];
#pragma unroll
    for (int i = 0; i < 2; i++)
#pragma unroll
        for (int j = 0; j < 4; j++)
#pragma unroll
            for (int r = 0; r < 4; r++) acc[i][j][r] = 0.f;

    int ar = tid >> 3, ac = (tid & 7) * 4;     // A tile loader: 16 rows/pass
    int br = tid >> 4, bc = (tid & 15) * 4;    // B tile loader: 8 rows/pass

    for (int k0 = 0; k0 < K; k0 += 32) {
#pragma unroll
        for (int i = 0; i < 4; i++) {
            float4 v = *(const float4*)(A + (size_t)(row0 + ar + i*16) * K + k0 + ac);
            v.x = to_tf32(v.x); v.y = to_tf32(v.y); v.z = to_tf32(v.z); v.w = to_tf32(v.w);
            *(float4*)&As[ar + i*16][ac] = v;
        }
#pragma unroll
        for (int i = 0; i < 4; i++) {
            float4 v = *(const float4*)(W + (size_t)(k0 + br + i*8) * Nout + col0 + bc);
            v.x = to_tf32(v.x); v.y = to_tf32(v.y); v.z = to_tf32(v.z); v.w = to_tf32(v.w);
            *(float4*)&Bs[br + i*8][bc] = v;
        }
        __syncthreads();

#pragma unroll
        for (int kk = 0; kk < 32; kk += 8) {
            uint32_t af[2][4], bf[4][2];
#pragma unroll
            for (int mt = 0; mt < 2; mt++) {
                int r = wm*32 + mt*16;
                af[mt][0] = fu(As[r + g    ][kk + tg    ]);
                af[mt][1] = fu(As[r + g + 8][kk + tg    ]);
                af[mt][2] = fu(As[r + g    ][kk + tg + 4]);
                af[mt][3] = fu(As[r + g + 8][kk + tg + 4]);
            }
#pragma unroll
            for (int nt = 0; nt < 4; nt++) {
                int c = wn*32 + nt*8;
                bf[nt][0] = fu(Bs[kk + tg    ][c + g]);
                bf[nt][1] = fu(Bs[kk + tg + 4][c + g]);
            }
#pragma unroll
            for (int mt = 0; mt < 2; mt++)
#pragma unroll
                for (int nt = 0; nt < 4; nt++)
                    mma8(acc[mt][nt], af[mt], bf[nt]);
        }
        __syncthreads();
    }

    // Epilogue: c0=(g,2tg) c1=(g,2tg+1) c2=(g+8,2tg) c3=(g+8,2tg+1)
#pragma unroll
    for (int mt = 0; mt < 2; mt++) {
#pragma unroll
        for (int nt = 0; nt < 4; nt++) {
#pragma unroll
            for (int rr = 0; rr < 4; rr++) {
                int r = row0 + wm*32 + mt*16 + g + ((rr >= 2) ? 8 : 0);
                int c = col0 + wn*32 + nt*8 + 2*tg + (rr & 1);
                float val = acc[mt][nt][rr] + bias[c];
                if (MODE == 0) {
                    // c in [0,768): which(256) | head(32) | d
                    int which = c >> 8, head = (c >> 5) & 7, d = c & 31;
                    int b = r >> 12, n = r & 4095;
                    size_t idx = ((size_t)(b*8 + head) * SEQ + n) * HD + d;
                    float* dst = (which == 0) ? g_q : (which == 1) ? g_k : g_v;
                    dst[idx] = val;
                } else {
                    Out[(size_t)r * 256 + c] = val;
                }
            }
        }
    }
}

// ---------------------------------------------------------------------------
// Flash attention (per (b,h)): O = softmax(Q K^T / sqrt(32)) V
// grid (SEQ/64, 16), 128 threads (4 warps, 16 q-rows each). Online softmax
// in base-2 (scale*log2(e) folded into Q). rel_bias dropped (softmax-invariant).
// ---------------------------------------------------------------------------
__global__ __launch_bounds__(128) void attn_kernel()
{
    __shared__ float Qs[64][36];
    __shared__ float Ks[64][36];       // B-frag pattern bank=4r+c: conflict-free
    __shared__ float Vs[64][40];       // B-frag pattern bank=8r+c: conflict-free
    __shared__ float Ps[4][16][68];    // per-warp P round-trip, A-frag conflict-free

    int tid = threadIdx.x, warp = tid >> 5, lane = tid & 31;
    int g = lane >> 2, tg = lane & 3;
    int bh = blockIdx.y;
    const float* qb = g_q + (size_t)bh * SEQ * HD;
    const float* kb = g_k + (size_t)bh * SEQ * HD;
    const float* vb = g_v + (size_t)bh * SEQ * HD;
    int q0 = blockIdx.x * 64;
    const float SCALE = 0.17677669529663687f * 1.4426950408889634f; // 1/sqrt(32)*log2(e)

    int ar = tid >> 3, ac = (tid & 7) * 4;

#pragma unroll
    for (int i = 0; i < 4; i++) {
        float4 v = *(const float4*)(qb + (size_t)(q0 + ar + i*16) * HD + ac);
        v.x = to_tf32(v.x * SCALE); v.y = to_tf32(v.y * SCALE);
        v.z = to_tf32(v.z * SCALE); v.w = to_tf32(v.w * SCALE);
        *(float4*)&Qs[ar + i*16][ac] = v;
    }
    __syncthreads();

    // Hoist Q fragments (constant over kv loop)
    uint32_t qf[4][4];
    {
        int r = warp * 16;
#pragma unroll
        for (int k4 = 0; k4 < 4; k4++) {
            int kk = k4 * 8;
            qf[k4][0] = fu(Qs[r + g    ][kk + tg    ]);
            qf[k4][1] = fu(Qs[r + g + 8][kk + tg    ]);
            qf[k4][2] = fu(Qs[r + g    ][kk + tg + 4]);
            qf[k4][3] = fu(Qs[r + g + 8][kk + tg + 4]);
        }
    }

    float m_i[2] = {-1e30f, -1e30f};
    float l_i[2] = {0.f, 0.f};
    float o[4][4];
#pragma unroll
    for (int i = 0; i < 4; i++)
#pragma unroll
        for (int j = 0; j < 4; j++) o[i][j] = 0.f;

    for (int kv = 0; kv < SEQ; kv += 64) {
#pragma unroll
        for (int i = 0; i < 4; i++) {
            float4 v = *(const float4*)(kb + (size_t)(kv + ar + i*16) * HD + ac);
            v.x = to_tf32(v.x); v.y = to_tf32(v.y); v.z = to_tf32(v.z); v.w = to_tf32(v.w);
            *(float4*)&Ks[ar + i*16][ac] = v;
            float4 w = *(const float4*)(vb + (size_t)(kv + ar + i*16) * HD + ac);
            w.x = to_tf32(w.x); w.y = to_tf32(w.y); w.z = to_tf32(w.z); w.w = to_tf32(w.w);
            *(float4*)&Vs[ar + i*16][ac] = w;
        }
        __syncthreads();

        // S = Q K^T  (warp: 16 x 64)
        float s[8][4];
#pragma unroll
        for (int nt = 0; nt < 8; nt++)
#pragma unroll
            for (int r = 0; r < 4; r++) s[nt][r] = 0.f;
#pragma unroll
        for (int k4 = 0; k4 < 4; k4++) {
            int kk = k4 * 8;
#pragma unroll
            for (int nt = 0; nt < 8; nt++) {
                uint32_t bf[2] = { fu(Ks[nt*8 + g][kk + tg]), fu(Ks[nt*8 + g][kk + tg + 4]) };
                mma8(s[nt], qf[k4], bf);
            }
        }

        // Online softmax (rows g and g+8). Quad (lanes 4g..4g+3) holds one row.
#pragma unroll
        for (int r2 = 0; r2 < 2; r2++) {
            float mt_ = -1e30f;
#pragma unroll
            for (int nt = 0; nt < 8; nt++)
                mt_ = fmaxf(mt_, fmaxf(s[nt][2*r2], s[nt][2*r2 + 1]));
            mt_ = fmaxf(mt_, __shfl_xor_sync(0xffffffffu, mt_, 1));
            mt_ = fmaxf(mt_, __shfl_xor_sync(0xffffffffu, mt_, 2));
            float mnew = fmaxf(m_i[r2], mt_);
            float alpha = ex2(m_i[r2] - mnew);
            m_i[r2] = mnew;
            float rs = 0.f;
#pragma unroll
            for (int nt = 0; nt < 8; nt++) {
                float p0 = ex2(s[nt][2*r2]     - mnew);
                float p1 = ex2(s[nt][2*r2 + 1] - mnew);
                s[nt][2*r2] = p0; s[nt][2*r2 + 1] = p1;
                rs += p0 + p1;
            }
            rs += __shfl_xor_sync(0xffffffffu, rs, 1);
            rs += __shfl_xor_sync(0xffffffffu, rs, 2);
            l_i[r2] = l_i[r2] * alpha + rs;
#pragma unroll
            for (int nt = 0; nt < 4; nt++) { o[nt][2*r2] *= alpha; o[nt][2*r2 + 1] *= alpha; }
        }

        // P: C-layout -> A-layout via warp-private smem round-trip
#pragma unroll
        for (int nt = 0; nt < 8; nt++) {
            float2 p0; p0.x = to_tf32(s[nt][0]); p0.y = to_tf32(s[nt][1]);
            *(float2*)&Ps[warp][g][nt*8 + 2*tg] = p0;
            float2 p1; p1.x = to_tf32(s[nt][2]); p1.y = to_tf32(s[nt][3]);
            *(float2*)&Ps[warp][g + 8][nt*8 + 2*tg] = p1;
        }
        __syncwarp();

        // O += P V   (warp: 16 x 32, K=64)
#pragma unroll
        for (int kc = 0; kc < 8; kc++) {
            uint32_t af[4] = {
                fu(Ps[warp][g    ][kc*8 + tg    ]),
                fu(Ps[warp][g + 8][kc*8 + tg    ]),
                fu(Ps[warp][g    ][kc*8 + tg + 4]),
                fu(Ps[warp][g + 8][kc*8 + tg + 4]) };
#pragma unroll
            for (int nt = 0; nt < 4; nt++) {
                uint32_t bf[2] = { fu(Vs[kc*8 + tg][nt*8 + g]), fu(Vs[kc*8 + tg + 4][nt*8 + g]) };
                mma8(o[nt], af, bf);
            }
        }
        __syncthreads();  // protect Ks/Vs/Ps before next tile
    }

    // Finalize: O /= l, write [b][n][h*32+d]
    int b = bh >> 3, h = bh & 7;
    float inv0 = 1.f / l_i[0], inv1 = 1.f / l_i[1];
    size_t base = (size_t)b * SEQ * 256 + h * HD;
    int rowa = q0 + warp * 16 + g;
#pragma unroll
    for (int nt = 0; nt < 4; nt++) {
        int d = nt*8 + 2*tg;
        g_o[base + (size_t)rowa       * 256 + d    ] = o[nt][0] * inv0;
        g_o[base + (size_t)rowa       * 256 + d + 1] = o[nt][1] * inv0;
        g_o[base + (size_t)(rowa + 8) * 256 + d    ] = o[nt][2] * inv1;
        g_o[base + (size_t)(rowa + 8) * 256 + d + 1] = o[nt][3] * inv1;
    }
}

// ---------------------------------------------------------------------------
extern "C" void kernel_launch(void* const* d_in, const int* in_sizes, int n_in,
                              void* d_out, int out_size)
{
    const float* x      = (const float*)d_in[0];  // [2,64,64,256]
    const float* w_qkv  = (const float*)d_in[1];  // [256,768]
    const float* b_qkv  = (const float*)d_in[2];  // [768]
    const float* w_proj = (const float*)d_in[3];  // [256,256]
    const float* b_proj = (const float*)d_in[4];  // [256]
    // d_in[5] = rel_bias: per-head scalar, softmax-invariant -> unused
    float* out = (float*)d_out;                   // [2,64,64,256] f32

    // QKV projection: [8192,256] x [256,768], scatter to q/k/v [bh][n][d]
    gemm_kernel<0><<<dim3(12, 128), 128>>>(x, w_qkv, b_qkv, nullptr, 8192, 768, 256);
    // Flash attention per (b,h)
    attn_kernel<<<dim3(SEQ / 64, BATCH * NH), 128>>>();
    // Output projection: [8192,256] x [256,256] -> d_out
    gemm_kernel<1><<<dim3(4, 128), 128>>>(nullptr, w_proj, b_proj, out, 8192, 256, 256);
}